// round 4
// baseline (speedup 1.0000x reference)
#include <cuda_runtime.h>
#include <math.h>

// Problem constants
#define B_  32
#define T_  2048
#define D_  512
#define H_  512
#define G_  2048          // 4*H
#define BT_ 65536         // B*T
#define NCTA_REC 128

// ---------------------------------------------------------------------------
// Scratch (device globals per harness rules: no cudaMalloc anywhere)
// ---------------------------------------------------------------------------
__device__ float g_xg[65536ULL * 2048ULL];   // (T, B, G) layout: xg[t][b][g]
__device__ float g_h[2][B_ * H_];            // double-buffered hidden state
__device__ unsigned g_flags[NCTA_REC];       // monotone per-CTA arrive flags
__device__ unsigned g_go[256];               // 8 replicated release words (stride 32)

__device__ __forceinline__ unsigned ld_acq_u32(const unsigned* p) {
    unsigned v;
    asm volatile("ld.acquire.gpu.global.u32 %0, [%1];" : "=r"(v) : "l"(p));
    return v;
}
__device__ __forceinline__ void st_rel_u32(unsigned* p, unsigned v) {
    asm volatile("st.release.gpu.global.u32 [%0], %1;" :: "l"(p), "r"(v));
}

// Blackwell packed fp32 FMA: one FFMA2 = 2 independent fp32 FMAs, rt=2.
__device__ __forceinline__ void ffma2(float2& d, float2 a, float2 b) {
    asm("fma.rn.f32x2 %0, %1, %2, %0;"
        : "+l"(reinterpret_cast<unsigned long long&>(d))
        : "l"(reinterpret_cast<unsigned long long&>(a)),
          "l"(reinterpret_cast<unsigned long long&>(b)));
}

// ---------------------------------------------------------------------------
// Kernel A: xg[t][b][g] = sum_d x[b][t][d] * W[d][g] + bias[g]
// fp32 FFMA2 GEMM, 128x128 tile, BK=8, 256 threads.
// i-row pairing: each f32x2 acc lane is one of two adjacent output rows, so
// per-output k-order (and results) match the scalar version bit-for-bit.
// W is stored column-duplicated in SMEM so no per-iteration packing is needed.
// Register double-buffer: next BK tile is fetched during compute.
// ---------------------------------------------------------------------------
#define WSD_STRIDE 264   // 256 dup floats + 8 pad

__global__ __launch_bounds__(256) void xg_gemm(const float* __restrict__ x,
                                               const float* __restrict__ W,
                                               const float* __restrict__ bias) {
    __shared__ float As[8][128];           // As[k][m], m contiguous
    __shared__ float Wsd[8][WSD_STRIDE];   // Wsd[k][2c]=Wsd[k][2c+1]=W[k][col+c]

    const int rowBase = blockIdx.y * 128;
    const int colBase = blockIdx.x * 128;
    const int tid = threadIdx.x;

    const int arow = tid >> 1;
    const int ak4  = (tid & 1) * 4;
    const int wrow = tid >> 5;
    const int wc4  = (tid & 31) * 4;
    const int tm   = (tid >> 4) * 8;
    const int tn   = (tid & 15) * 8;

    float2 acc2[4][8];
#pragma unroll
    for (int i = 0; i < 4; i++)
#pragma unroll
        for (int j = 0; j < 8; j++) acc2[i][j] = make_float2(0.f, 0.f);

    const float* xp = &x[(size_t)(rowBase + arow) * 512 + ak4];
    const float* wp = &W[(size_t)wrow * 2048 + colBase + wc4];

    // Prefetch tile 0
    float4 av = *(const float4*)&xp[0];
    float4 wv = *(const float4*)&wp[0];

    for (int k0 = 0; k0 < 512; k0 += 8) {
        // Store the prefetched tile
        As[ak4 + 0][arow] = av.x;
        As[ak4 + 1][arow] = av.y;
        As[ak4 + 2][arow] = av.z;
        As[ak4 + 3][arow] = av.w;
        *(float4*)&Wsd[wrow][2 * wc4]     = make_float4(wv.x, wv.x, wv.y, wv.y);
        *(float4*)&Wsd[wrow][2 * wc4 + 4] = make_float4(wv.z, wv.z, wv.w, wv.w);
        __syncthreads();

        // Prefetch next tile into registers (hidden under compute)
        if (k0 + 8 < 512) {
            av = *(const float4*)&xp[k0 + 8];
            wv = *(const float4*)&wp[(size_t)(k0 + 8) * 2048];
        }

#pragma unroll
        for (int kk = 0; kk < 8; kk++) {
            float4 a0 = *(const float4*)&As[kk][tm];
            float4 a1 = *(const float4*)&As[kk][tm + 4];
            float4 w0 = *(const float4*)&Wsd[kk][2 * tn];
            float4 w1 = *(const float4*)&Wsd[kk][2 * tn + 4];
            float4 w2 = *(const float4*)&Wsd[kk][2 * tn + 8];
            float4 w3 = *(const float4*)&Wsd[kk][2 * tn + 12];
            float2 A[4]  = { make_float2(a0.x, a0.y), make_float2(a0.z, a0.w),
                             make_float2(a1.x, a1.y), make_float2(a1.z, a1.w) };
            float2 Wp[8] = { make_float2(w0.x, w0.y), make_float2(w0.z, w0.w),
                             make_float2(w1.x, w1.y), make_float2(w1.z, w1.w),
                             make_float2(w2.x, w2.y), make_float2(w2.z, w2.w),
                             make_float2(w3.x, w3.y), make_float2(w3.z, w3.w) };
#pragma unroll
            for (int i2 = 0; i2 < 4; i2++)
#pragma unroll
                for (int j = 0; j < 8; j++)
                    ffma2(acc2[i2][j], A[i2], Wp[j]);
        }
        __syncthreads();
    }

    float bb[8];
    *(float4*)&bb[0] = *(const float4*)&bias[colBase + tn];
    *(float4*)&bb[4] = *(const float4*)&bias[colBase + tn + 4];

#pragma unroll
    for (int i2 = 0; i2 < 4; i2++) {
        int r0 = rowBase + tm + 2 * i2;      // lane .x
        int r1 = r0 + 1;                     // lane .y
        int t0 = r0 & (T_ - 1), b0 = r0 >> 11;
        int t1 = r1 & (T_ - 1), b1 = r1 >> 11;
        float* dst0 = &g_xg[((size_t)t0 * B_ + b0) * G_ + colBase + tn];
        float* dst1 = &g_xg[((size_t)t1 * B_ + b1) * G_ + colBase + tn];
        *(float4*)&dst0[0] = make_float4(acc2[i2][0].x + bb[0], acc2[i2][1].x + bb[1],
                                         acc2[i2][2].x + bb[2], acc2[i2][3].x + bb[3]);
        *(float4*)&dst0[4] = make_float4(acc2[i2][4].x + bb[4], acc2[i2][5].x + bb[5],
                                         acc2[i2][6].x + bb[6], acc2[i2][7].x + bb[7]);
        *(float4*)&dst1[0] = make_float4(acc2[i2][0].y + bb[0], acc2[i2][1].y + bb[1],
                                         acc2[i2][2].y + bb[2], acc2[i2][3].y + bb[3]);
        *(float4*)&dst1[4] = make_float4(acc2[i2][4].y + bb[4], acc2[i2][5].y + bb[5],
                                         acc2[i2][6].y + bb[6], acc2[i2][7].y + bb[7]);
    }
}

// ---------------------------------------------------------------------------
// Kernel B: persistent recurrence. CTA j owns h-columns [4j, 4j+4) -> 16 gate
// columns. Wh slice (two planes) + c-state live in SMEM for all 2048 steps.
// Dot products use FFMA2 with k-parity lane pairing (even/odd k partial sums).
// h exchanged via global double buffer + master-aggregated barrier with the
// release word replicated across 8 L2 lines.
// ---------------------------------------------------------------------------
#define WSTRIDE 516
#define SM_WA   0
#define SM_WB   (8 * WSTRIDE)
#define SM_HS   (16 * WSTRIDE)
#define SM_GS   (SM_HS + 32 * WSTRIDE)
#define SM_CS   (SM_GS + 512)
#define SMEM_FLOATS (SM_CS + 128)

__global__ __launch_bounds__(256) void lstm_rec(const float* __restrict__ W,
                                                const float* __restrict__ h0,
                                                const float* __restrict__ c0,
                                                float* __restrict__ out) {
    extern __shared__ float sm[];
    float* Wa = sm + SM_WA;          // Wa[g2][k]
    float* Wb = sm + SM_WB;          // Wb[g2][k]
    float* hs = sm + SM_HS;          // hs[b][k], stride WSTRIDE
    float* gs = sm + SM_GS;          // gs[gl*32 + b]
    float* cs = sm + SM_CS;          // cs[hcl*32 + b]

    const int tid = threadIdx.x;
    const int j   = blockIdx.x;      // 0..127
    const int jb  = j * 4;

    for (int e = tid; e < 8192; e += 256) {
        int k  = e >> 4;
        int gl = e & 15;
        int gcol = (gl >> 2) * 512 + jb + (gl & 3);
        float v = W[(size_t)(512 + k) * 2048 + gcol];
        float* plane = (gl & 1) ? Wb : Wa;
        plane[(gl >> 1) * WSTRIDE + k] = v;
    }
    if (tid < 128) {
        int b = tid >> 2, hcl = tid & 3;
        cs[hcl * 32 + b] = c0[b * 512 + jb + hcl];
    }
    // Barrier bases (uniform at run start; monotone across graph replays).
    const unsigned* mygo = &g_go[(j & 7) * 32];
    __shared__ unsigned s_fb, s_gb;
    if (tid == 0) {
        s_fb = *(volatile unsigned*)&g_flags[j];
        s_gb = *(volatile unsigned*)&mygo[0];
    }
    __syncthreads();
    const unsigned fbase = s_fb;
    const unsigned gbase = s_gb;

    const int b     = tid >> 3;            // 0..31
    const int g2    = tid & 7;             // 0..7
    const int gl0   = g2 * 2;
    const int gcol0 = (gl0 >> 2) * 512 + jb + (gl0 & 3);

    const float* wa = &Wa[g2 * WSTRIDE];
    const float* wb = &Wb[g2 * WSTRIDE];

    for (int t = 0; t < T_; t++) {
        // Prefetch xg for this thread (independent of h; streamed once)
        float2 xg2 = *(const float2*)&g_xg[((size_t)t * B_ + b) * G_ + gcol0];

        // Broadcast current h into SMEM (L2-only loads: no reuse, no staleness)
        const float* hsrc = (t == 0) ? h0 : g_h[t & 1];
        const float4* hsrc4 = (const float4*)hsrc;
        for (int i4 = tid; i4 < 4096; i4 += 256) {
            int bb = i4 >> 7, k4 = i4 & 127;
            *(float4*)&hs[bb * WSTRIDE + k4 * 4] = __ldcg(&hsrc4[bb * 128 + k4]);
        }
        __syncthreads();

        // Two K=512 dots per thread, FFMA2 with even/odd-k lane split:
        // 3x LDS.128 + 4x FFMA2 per 4 k.
        float2 accA = make_float2(xg2.x, 0.f);
        float2 accB = make_float2(xg2.y, 0.f);
        const float* hrow = &hs[b * WSTRIDE];
#pragma unroll 4
        for (int k = 0; k < 512; k += 4) {
            float4 h4 = *(const float4*)&hrow[k];
            float4 a4 = *(const float4*)&wa[k];
            float4 b4 = *(const float4*)&wb[k];
            ffma2(accA, make_float2(h4.x, h4.y), make_float2(a4.x, a4.y));
            ffma2(accB, make_float2(h4.x, h4.y), make_float2(b4.x, b4.y));
            ffma2(accA, make_float2(h4.z, h4.w), make_float2(a4.z, a4.w));
            ffma2(accB, make_float2(h4.z, h4.w), make_float2(b4.z, b4.w));
        }
        gs[gl0 * 32 + b]       = accA.x + accA.y;
        gs[(gl0 + 1) * 32 + b] = accB.x + accB.y;
        __syncthreads();

        // Gate combine: 128 threads, one (b, hcl) each
        if (tid < 128) {
            int bb = tid >> 2, hcl = tid & 3;
            float iv = gs[(0  + hcl) * 32 + bb];
            float fv = gs[(4  + hcl) * 32 + bb];
            float gv = gs[(8  + hcl) * 32 + bb];
            float ov = gs[(12 + hcl) * 32 + bb];
            iv = 1.f / (1.f + expf(-iv));
            fv = 1.f / (1.f + expf(-fv));
            gv = tanhf(gv);
            ov = 1.f / (1.f + expf(-ov));
            float c = fv * cs[hcl * 32 + bb] + iv * gv;
            cs[hcl * 32 + bb] = c;
            float h = ov * tanhf(c);
            g_h[(t + 1) & 1][bb * 512 + jb + hcl] = h;       // critical path
            out[((size_t)bb * T_ + t) * H_ + jb + hcl] = h;  // outputs[b][t][hc]
            if (t == T_ - 1) {
                out[(size_t)BT_ * H_ + bb * 512 + jb + hcl]           = h;  // h_T
                out[(size_t)BT_ * H_ + B_ * H_ + bb * 512 + jb + hcl] = c;  // c_T
            }
        }
        __syncthreads();   // all g_h stores done before the arrive below

        if (t < T_ - 1) {
            const unsigned step = (unsigned)t + 1u;
            if (tid == 0) st_rel_u32(&g_flags[j], fbase + step);  // arrive
            if (j == 0) {
                // Master: aggregate 128 flags (coalesced), then fan-out release.
                if (tid < NCTA_REC) {
                    while ((int)(ld_acq_u32(&g_flags[tid]) - (fbase + step)) < 0) { }
                }
                __syncthreads();
                if (tid < 8) st_rel_u32(&g_go[tid * 32], gbase + step);
            } else {
                // Others: one thread polls this CTA's replica of the release word.
                if (tid == 0) {
                    while ((int)(ld_acq_u32(&mygo[0]) - (gbase + step)) < 0) { }
                }
                __syncthreads();
            }
        }
    }
}

// ---------------------------------------------------------------------------
// Launcher
// ---------------------------------------------------------------------------
extern "C" void kernel_launch(void* const* d_in, const int* in_sizes, int n_in,
                              void* d_out, int out_size) {
    const float* x    = (const float*)d_in[0];   // (B, T, D)
    const float* W    = (const float*)d_in[1];   // (D+H, 4H)
    const float* bias = (const float*)d_in[2];   // (4H,)
    const float* h0   = (const float*)d_in[3];   // (B, H)
    const float* c0   = (const float*)d_in[4];   // (B, H)
    float* out = (float*)d_out;                  // outputs | h_T | c_T

    dim3 grid(G_ / 128, BT_ / 128);
    xg_gemm<<<grid, 256>>>(x, W, bias);

    size_t smem = SMEM_FLOATS * sizeof(float);
    cudaFuncSetAttribute(lstm_rec, cudaFuncAttributeMaxDynamicSharedMemorySize,
                         (int)smem);
    lstm_rec<<<NCTA_REC, 256, smem>>>(W, h0, c0, out);
}